// round 16
// baseline (speedup 1.0000x reference)
#include <cuda_runtime.h>
#include <stdint.h>

#define N_STRUCT   1000
#define ATOMS      100
#define N_SAMP     100000
#define N_GRAD     500000
#define DFEAT      128
#define NSEG       (N_STRUCT * ATOMS)      // 100000
#define ROW_F4     96                      // 3*128/4
#define GRAD_OUT_OFFSET (N_STRUCT * DFEAT)

#define WORK_NB    148                     // one block per SM, all co-resident
#define NTHR       1024
#define PREP_THREADS (WORK_NB * NTHR)      // 151552
#define TILE       680                     // scan tile (148*680 >= 100000)
#define NWARPS     (WORK_NB * 32)          // 4736
#define SEGS_PER_WARP 22                   // ceil(100000/4736)

// -------- scratch (device globals; zero-initialized at module load) --------
// Entry invariants (self-restored every call, barrier-ordered):
//   g_count==0, g_bsum==0, g_s1==0, g_s2==0; g_s3 reset in phase 1.
__device__ int g_count[NSEG];
__device__ int g_start[NSEG + 1];
__device__ int g_rows[N_GRAD];
__device__ int g_segpos[N_GRAD];   // (seg << 8) | within-segment rank
__device__ int g_bsum[WORK_NB];    // tile-sum + 1 (0 == not ready)
__device__ int g_s1, g_s2, g_s3;   // grid-sync counters

// ---------------------------------------------------------------------------
__device__ __forceinline__ void gridsync(int* ctr) {
    __syncthreads();
    if (threadIdx.x == 0) {
        __threadfence();
        atomicAdd(ctr, 1);
        volatile int* p = ctr;
        while (*p < WORK_NB) { }
    }
    __syncthreads();
}

// Warp-cooperative 32-ary lower_bound: first i with sid[i] >= target.
__device__ __forceinline__ int warp_lower_bound(const int* __restrict__ sid,
                                                int target, int lane) {
    int lo = 0, hi = N_SAMP;
    while (hi > lo) {
        int m    = hi - lo;
        int step = (m + 31) >> 5;
        int p    = lo + lane * step;
        bool pred = (p >= hi) ? true : (sid[p] >= target);
        unsigned bal = __ballot_sync(0xffffffffu, pred);
        int j = (bal == 0) ? 32 : (__ffs(bal) - 1);
        if (j == 0) { hi = lo; break; }
        int pj_1 = lo + (j - 1) * step;
        int pj   = lo + j * step;
        lo = pj_1 + 1;
        if (j < 32) { int nh = pj < hi ? pj : hi; hi = nh; }
    }
    return lo;
}

// ---------------------------------------------------------------------------
// ONE persistent kernel: 148 blocks x 1024 threads, all phases + gather.
// ---------------------------------------------------------------------------
__global__ __launch_bounds__(1024) void fused_kernel(
        const int*    __restrict__ gstruct,
        const int*    __restrict__ gatom,
        const float*  __restrict__ values,
        const int*    __restrict__ sid,
        const float4* __restrict__ grad4,
        float*        __restrict__ out,
        float*        __restrict__ out_grad) {
    int tid = threadIdx.x;
    int b   = blockIdx.x;
    int gth = b * NTHR + tid;
    int lane = tid & 31;
    int wid  = tid >> 5;

    // ---- phase 0: values boundaries (warps 0..8: lb(8b+w)), 9 per block ----
    __shared__ int s_bound[9];
    if (b == 0 && tid == 0) g_s3 = 0;      // reset before anyone reaches sync3
    int sbase = b * 8;
    if (wid < 9 && sbase + wid <= N_STRUCT && sbase < N_STRUCT) {
        int res = warp_lower_bound(sid, sbase + wid, lane);
        if (lane == 0) s_bound[wid] = res;
    }
    __syncthreads();

    // ---- phase 1a: values segment-sum (blocks 0..124; thread owns (sub,d)) --
    if (sbase < N_STRUCT) {
        int sub = tid >> 7;                // 0..7
        int d   = tid & 127;
        int s   = sbase + sub;
        if (s < N_STRUCT) {
            int lo = s_bound[sub], hi = s_bound[sub + 1];
            float a0 = 0.f, a1 = 0.f, a2 = 0.f, a3 = 0.f;
            float a4 = 0.f, a5 = 0.f, a6 = 0.f, a7 = 0.f;
            int r = lo;
            for (; r + 7 < hi; r += 8) {
                a0 += __ldcs(values + (long long)(r    ) * DFEAT + d);
                a1 += __ldcs(values + (long long)(r + 1) * DFEAT + d);
                a2 += __ldcs(values + (long long)(r + 2) * DFEAT + d);
                a3 += __ldcs(values + (long long)(r + 3) * DFEAT + d);
                a4 += __ldcs(values + (long long)(r + 4) * DFEAT + d);
                a5 += __ldcs(values + (long long)(r + 5) * DFEAT + d);
                a6 += __ldcs(values + (long long)(r + 6) * DFEAT + d);
                a7 += __ldcs(values + (long long)(r + 7) * DFEAT + d);
            }
            for (; r < hi; ++r)
                a0 += __ldcs(values + (long long)r * DFEAT + d);
            float acc = ((a0 + a1) + (a2 + a3)) + ((a4 + a5) + (a6 + a7));
            __stcs(out + (long long)s * DFEAT + d, acc);
        }
    }

    // ---- phase 1b: degree count; atomicAdd return value = rank ----
    for (int r = gth; r < N_GRAD; r += PREP_THREADS) {
        int seg = __ldcs(gstruct + r) * ATOMS + __ldcs(gatom + r);
        int pos = atomicAdd(&g_count[seg], 1);
        g_segpos[r] = (seg << 8) | pos;    // pos <= ~25
    }
    gridsync(&g_s1);

    // ---- phase 2: tile scan (680/block) + decoupled lookback ----
    {
        __shared__ int sh[NTHR];
        __shared__ int s_boff;
        int i = b * TILE + tid;
        int v = (tid < TILE && i < NSEG) ? g_count[i] : 0;
        sh[tid] = v;
        __syncthreads();
        for (int off = 1; off < NTHR; off <<= 1) {
            int t = (tid >= off) ? sh[tid - off] : 0;
            __syncthreads();
            sh[tid] += t;
            __syncthreads();
        }
        if (tid == NTHR - 1) {
            volatile int* p = g_bsum;
            p[b] = sh[NTHR - 1] + 1;       // tile total (+1 = ready)
        }
        if (tid < 32) {                    // lookback j < b
            int acc = 0;
            volatile int* p = g_bsum;
            for (int j = tid; j < b; j += 32) {
                int w;
                while ((w = p[j]) == 0) { }
                acc += w - 1;
            }
            #pragma unroll
            for (int off = 16; off > 0; off >>= 1)
                acc += __shfl_down_sync(0xffffffffu, acc, off);
            if (tid == 0) s_boff = acc;
        }
        __syncthreads();
        if (tid < TILE && i < NSEG) g_start[i] = sh[tid] - v + s_boff;
        if (i == NSEG - 1) g_start[NSEG] = N_GRAD;
    }
    gridsync(&g_s2);

    // ---- phase 3: atomic-free scatter + invariant resets ----
    if (b == 0 && tid == 0) g_s1 = 0;      // all blocks passed sync1
    if (b == 0 && tid < WORK_NB) g_bsum[tid] = 0;
    for (int z = gth; z < NSEG; z += PREP_THREADS) g_count[z] = 0;
    for (int r = gth; r < N_GRAD; r += PREP_THREADS) {
        int sp  = g_segpos[r];
        g_rows[g_start[sp >> 8] + (sp & 255)] = r;
    }
    gridsync(&g_s3);

    // ---- phase 4: persistent gather — proven inner loop, 22 segs/warp ----
    if (b == 0 && tid == 0) g_s2 = 0;      // all blocks passed sync2
    int w = b * 32 + wid;                  // 0..4735
    int seg0 = w * SEGS_PER_WARP;
    if (seg0 >= NSEG) return;
    int seg1 = seg0 + SEGS_PER_WARP;
    if (seg1 > NSEG) seg1 = NSEG;

    int lo = g_start[seg0];
    for (int seg = seg0; seg < seg1; ++seg) {
        int hi  = g_start[seg + 1];
        int cnt = hi - lo;

        int rid = (lane < cnt) ? g_rows[lo + lane] : 0;

        float4 a0 = make_float4(0.f, 0.f, 0.f, 0.f);
        float4 a1 = a0, a2 = a0;

        int n32 = cnt < 32 ? cnt : 32;
        #pragma unroll 4
        for (int p = 0; p < n32; ++p) {
            long long row = __shfl_sync(0xffffffffu, rid, p);
            const float4* src = grad4 + row * ROW_F4;
            float4 v0 = __ldcs(src + lane);
            float4 v1 = __ldcs(src + lane + 32);
            float4 v2 = __ldcs(src + lane + 64);
            a0.x += v0.x; a0.y += v0.y; a0.z += v0.z; a0.w += v0.w;
            a1.x += v1.x; a1.y += v1.y; a1.z += v1.z; a1.w += v1.w;
            a2.x += v2.x; a2.y += v2.y; a2.z += v2.z; a2.w += v2.w;
        }
        for (int p = 32; p < cnt; ++p) {   // overflow fallback (never hit)
            long long row = g_rows[lo + p];
            const float4* src = grad4 + row * ROW_F4;
            float4 v0 = __ldcs(src + lane);
            float4 v1 = __ldcs(src + lane + 32);
            float4 v2 = __ldcs(src + lane + 64);
            a0.x += v0.x; a0.y += v0.y; a0.z += v0.z; a0.w += v0.w;
            a1.x += v1.x; a1.y += v1.y; a1.z += v1.z; a1.w += v1.w;
            a2.x += v2.x; a2.y += v2.y; a2.z += v2.z; a2.w += v2.w;
        }

        float4* dst = (float4*)(out_grad + (long long)seg * (3 * DFEAT));
        __stcs(dst + lane,      a0);
        __stcs(dst + lane + 32, a1);
        __stcs(dst + lane + 64, a2);

        lo = hi;
    }
}

// ---------------------------------------------------------------------------
extern "C" void kernel_launch(void* const* d_in, const int* in_sizes, int n_in,
                              void* d_out, int out_size) {
    const float*  values  = (const float*)d_in[0];
    const int*    sid     = (const int*)  d_in[1];
    const float4* grad4   = (const float4*)d_in[2];
    const int*    gstruct = (const int*)  d_in[3];
    const int*    gatom   = (const int*)  d_in[4];

    float* out      = (float*)d_out;
    float* out_grad = out + GRAD_OUT_OFFSET;

    fused_kernel<<<WORK_NB, NTHR>>>(gstruct, gatom, values, sid,
                                    grad4, out, out_grad);
}

// round 17
// speedup vs baseline: 1.0814x; 1.0814x over previous
#include <cuda_runtime.h>
#include <stdint.h>

#define N_STRUCT   1000
#define ATOMS      100
#define N_SAMP     100000
#define N_GRAD     500000
#define DFEAT      128
#define NSEG       (N_STRUCT * ATOMS)      // 100000
#define ROW_F4     96                      // 3*128/4
#define GRAD_OUT_OFFSET (N_STRUCT * DFEAT)

// prep: 148 worker blocks (1/SM), tile 680 segments each (148*680 >= 100000)
#define WORK_NB    148
#define TILE       680
#define PREP_THREADS (WORK_NB * 1024)          // 151552

#define VALUES_NB  ((N_STRUCT + 7) / 8)        // 125
#define PREP_BLOCKS (WORK_NB + VALUES_NB)      // 273 (all co-resident)

// gather: 512-thread blocks (16 warps, 1 seg/warp) -> 2 blocks/SM = 32 warps
#define GATHER_TPB    512
#define GATHER_BLOCKS (NSEG / 16)              // 6250

// -------- scratch (device globals; zero-initialized at module load) --------
// Invariants at kernel_launch entry (restored by gather every call):
//   g_count == 0, g_bsum == 0, g_sync1 == 0, g_sync2 == 0
__device__ int g_count[NSEG];
__device__ int g_start[NSEG + 1];
__device__ int g_rows[N_GRAD];
__device__ int g_segpos[N_GRAD];   // (seg << 8) | within-segment rank
__device__ int g_bsum[WORK_NB];    // tile-sum + 1 (0 == not ready)
__device__ int g_sync1, g_sync2;   // grid-sync counters (worker blocks only)

// ---------------------------------------------------------------------------
// Kernel 1 (persistent prep) — byte-identical to R11 (best measured):
//   bid <  WORK_NB : count -> gridsync -> scan(+lookback) -> gridsync -> scatter
//   bid >= WORK_NB : values segment-sums (no sync participation)
// ---------------------------------------------------------------------------
__global__ __launch_bounds__(1024) void prep_kernel(
        const int*   __restrict__ gstruct,
        const int*   __restrict__ gatom,
        const float* __restrict__ values,
        const int*   __restrict__ sid,
        float*       __restrict__ out) {
    if (blockIdx.x < WORK_NB) {
        int tid = threadIdx.x;
        int b   = blockIdx.x;
        int gth = b * 1024 + tid;

        // --- phase 1: degree count; atomicAdd return value = rank ---
        for (int r = gth; r < N_GRAD; r += PREP_THREADS) {
            int seg = __ldcs(gstruct + r) * ATOMS + __ldcs(gatom + r);
            int pos = atomicAdd(&g_count[seg], 1);
            g_segpos[r] = (seg << 8) | pos;          // pos <= ~25
        }
        __syncthreads();
        if (tid == 0) {
            __threadfence();
            atomicAdd(&g_sync1, 1);
            volatile int* p = &g_sync1;
            while (*p < WORK_NB) { }
        }
        __syncthreads();

        // --- phase 2: tile scan (680 segs/block) + decoupled lookback ---
        __shared__ int sh[1024];
        __shared__ int s_boff;
        int i = b * TILE + tid;                      // tid < TILE valid
        int v = (tid < TILE && i < NSEG) ? g_count[i] : 0;
        sh[tid] = v;
        __syncthreads();
        for (int off = 1; off < 1024; off <<= 1) {
            int t = (tid >= off) ? sh[tid - off] : 0;
            __syncthreads();
            sh[tid] += t;
            __syncthreads();
        }
        if (tid == 1023) {
            volatile int* p = g_bsum;
            p[b] = sh[1023] + 1;                     // tile total (+1 = ready)
        }
        if (tid < 32) {                               // lookback j < b
            int acc = 0;
            volatile int* p = g_bsum;
            for (int j = tid; j < b; j += 32) {
                int w;
                while ((w = p[j]) == 0) { }
                acc += w - 1;
            }
            #pragma unroll
            for (int off = 16; off > 0; off >>= 1)
                acc += __shfl_down_sync(0xffffffffu, acc, off);
            if (tid == 0) s_boff = acc;
        }
        __syncthreads();
        if (tid < TILE && i < NSEG) g_start[i] = sh[tid] - v + s_boff;
        if (i == NSEG - 1) g_start[NSEG] = N_GRAD;

        __syncthreads();
        if (tid == 0) {
            __threadfence();
            atomicAdd(&g_sync2, 1);
            volatile int* p = &g_sync2;
            while (*p < WORK_NB) { }
        }
        __syncthreads();

        // --- phase 3: atomic-free scatter ---
        for (int r = gth; r < N_GRAD; r += PREP_THREADS) {
            int sp  = g_segpos[r];
            int seg = sp >> 8;
            g_rows[g_start[seg] + (sp & 255)] = r;
        }
    } else {
        // --- values segment-sum: 8 structures per block (sorted -> bsearch)
        int vb  = blockIdx.x - WORK_NB;
        int sub = threadIdx.x >> 7;            // 0..7
        int d   = threadIdx.x & 127;
        int s   = vb * 8 + sub;

        __shared__ int s_lo[8], s_hi[8];
        if (s < N_STRUCT) {
            if (d == 0) {
                int lo = 0, hi = N_SAMP;
                while (lo < hi) { int m = (lo + hi) >> 1; if (sid[m] < s) lo = m + 1; else hi = m; }
                s_lo[sub] = lo;
                lo = s_lo[sub]; hi = N_SAMP;
                while (lo < hi) { int m = (lo + hi) >> 1; if (sid[m] < s + 1) lo = m + 1; else hi = m; }
                s_hi[sub] = lo;
            }
        }
        __syncthreads();
        if (s >= N_STRUCT) return;

        int lo = s_lo[sub], hi = s_hi[sub];
        float a0 = 0.f, a1 = 0.f, a2 = 0.f, a3 = 0.f;
        int r = lo;
        for (; r + 3 < hi; r += 4) {
            a0 += __ldcs(values + (long long)(r    ) * DFEAT + d);
            a1 += __ldcs(values + (long long)(r + 1) * DFEAT + d);
            a2 += __ldcs(values + (long long)(r + 2) * DFEAT + d);
            a3 += __ldcs(values + (long long)(r + 3) * DFEAT + d);
        }
        for (; r < hi; ++r)
            a0 += __ldcs(values + (long long)r * DFEAT + d);
        __stcs(out + (long long)s * DFEAT + d, (a0 + a1) + (a2 + a3));
    }
}

// ---------------------------------------------------------------------------
// Kernel 2: gather-reduce — proven inner loop; 512-thread blocks so 2 CTAs/SM
// fit at 52 regs (32 warps resident vs 26). One warp per segment; row ids
// prefetched into lanes + shfl broadcast. Restores all scratch invariants.
// ---------------------------------------------------------------------------
__global__ __launch_bounds__(GATHER_TPB) void gather_kernel(
        const float4* __restrict__ grad4,
        float*        __restrict__ out_grad) {
    int zi = blockIdx.x * GATHER_TPB + threadIdx.x;
    if (zi < NSEG) g_count[zi] = 0;
    if (zi < WORK_NB) g_bsum[zi] = 0;
    if (zi == 0) { g_sync1 = 0; g_sync2 = 0; }

    int warp_id = (blockIdx.x * GATHER_TPB + threadIdx.x) >> 5;
    int lane    = threadIdx.x & 31;

    int lo  = g_start[warp_id];
    int hi  = g_start[warp_id + 1];
    int cnt = hi - lo;

    int rid = (lane < cnt) ? g_rows[lo + lane] : 0;

    float4 a0 = make_float4(0.f, 0.f, 0.f, 0.f);
    float4 a1 = a0, a2 = a0;

    int n32 = cnt < 32 ? cnt : 32;
    #pragma unroll 4
    for (int p = 0; p < n32; ++p) {
        long long row = __shfl_sync(0xffffffffu, rid, p);
        const float4* src = grad4 + row * ROW_F4;
        float4 v0 = __ldcs(src + lane);
        float4 v1 = __ldcs(src + lane + 32);
        float4 v2 = __ldcs(src + lane + 64);
        a0.x += v0.x; a0.y += v0.y; a0.z += v0.z; a0.w += v0.w;
        a1.x += v1.x; a1.y += v1.y; a1.z += v1.z; a1.w += v1.w;
        a2.x += v2.x; a2.y += v2.y; a2.z += v2.z; a2.w += v2.w;
    }
    for (int p = 32; p < cnt; ++p) {         // overflow fallback (never hit)
        long long row = g_rows[lo + p];
        const float4* src = grad4 + row * ROW_F4;
        float4 v0 = __ldcs(src + lane);
        float4 v1 = __ldcs(src + lane + 32);
        float4 v2 = __ldcs(src + lane + 64);
        a0.x += v0.x; a0.y += v0.y; a0.z += v0.z; a0.w += v0.w;
        a1.x += v1.x; a1.y += v1.y; a1.z += v1.z; a1.w += v1.w;
        a2.x += v2.x; a2.y += v2.y; a2.z += v2.z; a2.w += v2.w;
    }

    float4* dst = (float4*)(out_grad + (long long)warp_id * (3 * DFEAT));
    __stcs(dst + lane,      a0);
    __stcs(dst + lane + 32, a1);
    __stcs(dst + lane + 64, a2);
}

// ---------------------------------------------------------------------------
extern "C" void kernel_launch(void* const* d_in, const int* in_sizes, int n_in,
                              void* d_out, int out_size) {
    const float*  values  = (const float*)d_in[0];
    const int*    sid     = (const int*)  d_in[1];
    const float4* grad4   = (const float4*)d_in[2];
    const int*    gstruct = (const int*)  d_in[3];
    const int*    gatom   = (const int*)  d_in[4];

    float* out      = (float*)d_out;
    float* out_grad = out + GRAD_OUT_OFFSET;

    prep_kernel<<<PREP_BLOCKS, 1024>>>(gstruct, gatom, values, sid, out);
    gather_kernel<<<GATHER_BLOCKS, GATHER_TPB>>>(grad4, out_grad);
}